// round 1
// baseline (speedup 1.0000x reference)
#include <cuda_runtime.h>
#include <math.h>

// Grid / problem constants (match reference)
#define NG    320
#define NS1   (NG*NG)          // cells per shot
#define NSHOT 2
#define NSRC  8
#define NREC  96
#define NT    160
#define NSA   (NSHOT*NS1)      // cells total (both shots)
#define PML_W 20

__device__ float g_f[13*NSA];        // 13 state fields, ~10.65 MB
__device__ float g_by[NG];
__device__ float g_bx[NG];
__device__ float g_recs[NT*NSHOT*NREC];

// field offsets within g_f (units of NSA)
// 0 vy, 1 vx, 2 syy, 3 sxy, 4 sxx,
// 5 mvyy, 6 mvyx, 7 mvxy, 8 mvxx,
// 9 msyyy, 10 msxyy, 11 msxyx, 12 msxxx

__device__ __forceinline__ float c1f() { return 1.125f; }
__device__ __forceinline__ float c2f() { return (float)(-1.0/24.0); }
#define IDHF 0.25f
#define DTF  4.0e-4f

__global__ void init_pml_kernel()
{
    int i = threadIdx.x;
    if (i >= NG) return;
    const double d0 = 3.0 * 1600.0 * log(1000.0) / (2.0 * PML_W * 4.0);
    double d = 0.0;
    if (i < PML_W) {
        double a = ((double)(PML_W - i)) / PML_W;
        d = d0 * a * a;
    } else if (i >= NG - PML_W) {
        double a = ((double)i - (NG - 1 - PML_W)) / PML_W;
        d = d0 * a * a;
    }
    float b = (float)exp(-d * 4.0e-4);
    g_by[i] = b;
    g_bx[i] = b;
}

__global__ __launch_bounds__(256) void vel_kernel(
    const float* __restrict__ buoy,
    const float* __restrict__ amps,   // [NSHOT, NSRC, NT]
    const int*   __restrict__ sloc,   // [NSHOT, NSRC, 2]
    int t)
{
    int x  = blockIdx.x * 32 + threadIdx.x;
    int gy = blockIdx.y * 8  + threadIdx.y;
    int b  = (gy >= NG) ? 1 : 0;
    int y  = gy - b * NG;
    int base = b * NS1;
    int row  = y * NG;
    int idx  = base + row + x;

    int ym1 = (y + NG - 1) % NG, ym2 = (y + NG - 2) % NG;
    int yp1 = (y + 1) % NG,      yp2 = (y + 2) % NG;
    int xm1 = (x + NG - 1) % NG, xm2 = (x + NG - 2) % NG;
    int xp1 = (x + 1) % NG,      xp2 = (x + 2) % NG;

    const float C1 = c1f(), C2 = c2f();
    const float* __restrict__ syy = g_f + 2*NSA;
    const float* __restrict__ sxy = g_f + 3*NSA;
    const float* __restrict__ sxx = g_f + 4*NSA;

    float byv = g_by[y];
    float bxv = g_bx[x];
    float bv  = buoy[row + x];

    // d = Dy^-(syy); msyyy update; ay = d + msyyy
    float d = (C1 * (syy[idx] - syy[base + ym1*NG + x])
             + C2 * (syy[base + yp1*NG + x] - syy[base + ym2*NG + x])) * IDHF;
    float* __restrict__ msyyy = g_f + 9*NSA;
    float m = msyyy[idx];
    m = byv * m + (byv - 1.0f) * d;
    msyyy[idx] = m;
    float ay = d + m;

    // d = Dx^+(sxy); msxyx update
    d = (C1 * (sxy[base + row + xp1] - sxy[idx])
       + C2 * (sxy[base + row + xp2] - sxy[base + row + xm1])) * IDHF;
    float* __restrict__ msxyx = g_f + 11*NSA;
    m = msxyx[idx];
    m = bxv * m + (bxv - 1.0f) * d;
    msxyx[idx] = m;
    ay += d + m;

    float vy = g_f[0*NSA + idx] + DTF * bv * ay;

    // d = Dx^-(sxx); msxxx update; ax = d + msxxx
    d = (C1 * (sxx[idx] - sxx[base + row + xm1])
       + C2 * (sxx[base + row + xp1] - sxx[base + row + xm2])) * IDHF;
    float* __restrict__ msxxx = g_f + 12*NSA;
    m = msxxx[idx];
    m = bxv * m + (bxv - 1.0f) * d;
    msxxx[idx] = m;
    float ax = d + m;

    // d = Dy^+(sxy); msxyy update
    d = (C1 * (sxy[base + yp1*NG + x] - sxy[idx])
       + C2 * (sxy[base + yp2*NG + x] - sxy[base + ym1*NG + x])) * IDHF;
    float* __restrict__ msxyy = g_f + 10*NSA;
    m = msxyy[idx];
    m = byv * m + (byv - 1.0f) * d;
    msxyy[idx] = m;
    ax += d + m;

    float vx = g_f[1*NSA + idx] + DTF * bv * ax;

    // source injection into vy (src_buoy == buoyancy at this cell == bv)
#pragma unroll
    for (int s = 0; s < NSRC; s++) {
        int sy = sloc[(b*NSRC + s)*2 + 0];
        int sx = sloc[(b*NSRC + s)*2 + 1];
        if (sy == y && sx == x)
            vy += DTF * amps[(b*NSRC + s)*NT + t] * bv;
    }

    float mk = (y < 2 || y >= NG-2 || x < 2 || x >= NG-2) ? 0.0f : 1.0f;
    g_f[0*NSA + idx] = vy * mk;
    g_f[1*NSA + idx] = vx * mk;
}

__global__ __launch_bounds__(256) void stress_kernel(
    const float* __restrict__ lamb,
    const float* __restrict__ mu,
    const int*   __restrict__ rloc,   // [NSHOT, NREC, 2]
    int t)
{
    int x  = blockIdx.x * 32 + threadIdx.x;
    int gy = blockIdx.y * 8  + threadIdx.y;

    // receiver recording (vy is read-only in this kernel -> race-free)
    if (blockIdx.x == 0 && blockIdx.y == 0) {
        int tid = threadIdx.y * 32 + threadIdx.x;
        if (tid < NSHOT*NREC) {
            int rb = tid / NREC, r = tid % NREC;
            int ry = rloc[(rb*NREC + r)*2 + 0];
            int rx = rloc[(rb*NREC + r)*2 + 1];
            g_recs[(t*NSHOT + rb)*NREC + r] = g_f[0*NSA + rb*NS1 + ry*NG + rx];
        }
    }

    int b  = (gy >= NG) ? 1 : 0;
    int y  = gy - b * NG;
    int base = b * NS1;
    int row  = y * NG;
    int idx  = base + row + x;

    int ym1 = (y + NG - 1) % NG, ym2 = (y + NG - 2) % NG;
    int yp1 = (y + 1) % NG,      yp2 = (y + 2) % NG;
    int xm1 = (x + NG - 1) % NG, xm2 = (x + NG - 2) % NG;
    int xp1 = (x + 1) % NG,      xp2 = (x + 2) % NG;

    const float C1 = c1f(), C2 = c2f();
    const float* __restrict__ vy = g_f + 0*NSA;
    const float* __restrict__ vx = g_f + 1*NSA;

    float byv = g_by[y];
    float bxv = g_bx[x];
    float lam = lamb[row + x];
    float muv = mu[row + x];
    float l2m = lam + 2.0f * muv;

    // e1 = Dy^+(vy) + mvyy
    float d = (C1 * (vy[base + yp1*NG + x] - vy[idx])
             + C2 * (vy[base + yp2*NG + x] - vy[base + ym1*NG + x])) * IDHF;
    float* __restrict__ mvyy = g_f + 5*NSA;
    float m = mvyy[idx];
    m = byv * m + (byv - 1.0f) * d;
    mvyy[idx] = m;
    float e1 = d + m;

    // e2 = Dx^-(vx) + mvxx
    d = (C1 * (vx[idx] - vx[base + row + xm1])
       + C2 * (vx[base + row + xp1] - vx[base + row + xm2])) * IDHF;
    float* __restrict__ mvxx = g_f + 8*NSA;
    m = mvxx[idx];
    m = bxv * m + (bxv - 1.0f) * d;
    mvxx[idx] = m;
    float e2 = d + m;

    float mk = (y < 2 || y >= NG-2 || x < 2 || x >= NG-2) ? 0.0f : 1.0f;

    float syy = (g_f[2*NSA + idx] + DTF * (l2m * e1 + lam * e2)) * mk;
    float sxx = (g_f[4*NSA + idx] + DTF * (l2m * e2 + lam * e1)) * mk;
    g_f[2*NSA + idx] = syy;
    g_f[4*NSA + idx] = sxx;

    // g = Dx^+(vy) + mvyx
    d = (C1 * (vy[base + row + xp1] - vy[idx])
       + C2 * (vy[base + row + xp2] - vy[base + row + xm1])) * IDHF;
    float* __restrict__ mvyx = g_f + 6*NSA;
    m = mvyx[idx];
    m = bxv * m + (bxv - 1.0f) * d;
    mvyx[idx] = m;
    float g = d + m;

    // g += Dy^-(vx) + mvxy
    d = (C1 * (vx[idx] - vx[base + ym1*NG + x])
       + C2 * (vx[base + yp1*NG + x] - vx[base + ym2*NG + x])) * IDHF;
    float* __restrict__ mvxy = g_f + 7*NSA;
    m = mvxy[idx];
    m = byv * m + (byv - 1.0f) * d;
    mvxy[idx] = m;
    g += d + m;

    g_f[3*NSA + idx] = (g_f[3*NSA + idx] + DTF * muv * g) * mk;
}

__global__ void finalize_kernel(float* __restrict__ out)
{
    int i = blockIdx.x * 256 + threadIdx.x;
    const int total = NSHOT * NREC * (NT - 1);
    if (i >= total) return;
    int t = i % (NT - 1);
    int r = (i / (NT - 1)) % NREC;
    int b = i / ((NT - 1) * NREC);
    out[i] = (g_recs[((t + 1)*NSHOT + b)*NREC + r]
            + g_recs[(t      *NSHOT + b)*NREC + r]) * 0.5f;
}

extern "C" void kernel_launch(void* const* d_in, const int* in_sizes, int n_in,
                              void* d_out, int out_size)
{
    const float* lamb = (const float*)d_in[0];
    const float* mu   = (const float*)d_in[1];
    const float* buoy = (const float*)d_in[2];
    const float* amps = (const float*)d_in[3];
    const int*   sloc = (const int*)d_in[4];
    const int*   rloc = (const int*)d_in[5];
    float* out = (float*)d_out;

    void* pstate = nullptr;
    cudaGetSymbolAddress(&pstate, g_f);
    cudaMemsetAsync(pstate, 0, sizeof(float) * 13 * NSA);

    init_pml_kernel<<<1, NG>>>();

    dim3 blk(32, 8);
    dim3 grd(NG / 32, (NSHOT * NG) / 8);
    for (int t = 0; t < NT; t++) {
        vel_kernel<<<grd, blk>>>(buoy, amps, sloc, t);
        stress_kernel<<<grd, blk>>>(lamb, mu, rloc, t);
    }

    const int total = NSHOT * NREC * (NT - 1);
    finalize_kernel<<<(total + 255) / 256, 256>>>(out);
}

// round 2
// speedup vs baseline: 1.0091x; 1.0091x over previous
#include <cuda_runtime.h>
#include <math.h>

#define NG    320
#define NS1   (NG*NG)
#define NSHOT 2
#define NSRC  8
#define NREC  96
#define NT    160
#define PML_W 20
#define NBLK  400
#define TPB   256
#define IDHF  0.25f
#define DTF   4.0e-4f

// Global state: only the 5 wave fields (neighbors read them). CPML memory
// variables live in registers of the owning thread.
__device__ float g_vy [NSHOT*NS1];
__device__ float g_vx [NSHOT*NS1];
__device__ float g_syy[NSHOT*NS1];
__device__ float g_sxy[NSHOT*NS1];
__device__ float g_sxx[NSHOT*NS1];
__device__ float g_recs[NT*NSHOT*NREC];

__device__ unsigned g_count = 0;
__device__ volatile unsigned g_phase = 0;

// Grid-wide barrier, cooperative-groups pattern. g_phase increases
// monotonically across graph replays; targets are relative to start value.
__device__ __forceinline__ void gbar(unsigned target)
{
    __syncthreads();
    if (threadIdx.x == 0) {
        __threadfence();
        if (atomicAdd(&g_count, 1u) == NBLK - 1) {
            g_count = 0;
            __threadfence();
            g_phase = target;
        } else {
            while ((int)(g_phase - target) < 0) { }
        }
        __threadfence();
    }
    __syncthreads();
}

__device__ __forceinline__ float pml_b(int i)
{
    const double d0 = 3.0 * 1600.0 * log(1000.0) / (2.0 * PML_W * 4.0);
    double dd = 0.0;
    if (i < PML_W) {
        double a = (double)(PML_W - i) / PML_W;
        dd = d0 * a * a;
    } else if (i >= NG - PML_W) {
        double a = ((double)i - (NG - 1 - PML_W)) / PML_W;
        dd = d0 * a * a;
    }
    return (float)exp(-dd * 4.0e-4);
}

__global__ __launch_bounds__(TPB, 3) void sim_kernel(
    const float* __restrict__ lamb,
    const float* __restrict__ mu,
    const float* __restrict__ buoy,
    const float* __restrict__ amps,   // [NSHOT, NSRC, NT]
    const int*   __restrict__ sloc,   // [NSHOT, NSRC, 2]
    const int*   __restrict__ rloc,   // [NSHOT, NREC, 2]
    float* __restrict__ out)          // [NSHOT, NREC, NT-1]
{
    const int cid = blockIdx.x * TPB + threadIdx.x;   // 0..NS1-1
    const int y = cid / NG;
    const int x = cid - y * NG;
    unsigned ph = g_phase;   // base phase from previous replay (monotonic)

    // wrapped neighbor coordinates (wrap only matters at masked border cells)
    const int ym1 = (y == 0)      ? NG - 1      : y - 1;
    const int ym2 = (y <= 1)      ? y + NG - 2  : y - 2;
    const int yp1 = (y == NG - 1) ? 0           : y + 1;
    const int yp2 = (y >= NG - 2) ? y - (NG-2)  : y + 2;
    const int xm1 = (x == 0)      ? NG - 1      : x - 1;
    const int xm2 = (x <= 1)      ? x + NG - 2  : x - 2;
    const int xp1 = (x == NG - 1) ? 0           : x + 1;
    const int xp2 = (x >= NG - 2) ? x - (NG-2)  : x + 2;

    const int o    = y * NG + x;
    const int oym1 = ym1 * NG + x, oym2 = ym2 * NG + x;
    const int oyp1 = yp1 * NG + x, oyp2 = yp2 * NG + x;
    const int oxm1 = y * NG + xm1, oxm2 = y * NG + xm2;
    const int oxp1 = y * NG + xp1, oxp2 = y * NG + xp2;

    const float byv = pml_b(y);
    const float bxv = pml_b(x);
    const float bv  = buoy[o];
    const float lam = lamb[o];
    const float muv = mu[o];
    const float l2m = lam + 2.0f * muv;
    const float mk  = (y < 2 || y >= NG-2 || x < 2 || x >= NG-2) ? 0.0f : 1.0f;

    // source membership bitmasks (per shot)
    unsigned smask0 = 0, smask1 = 0;
#pragma unroll
    for (int s = 0; s < NSRC; s++) {
        if (sloc[(0*NSRC + s)*2] == y && sloc[(0*NSRC + s)*2 + 1] == x) smask0 |= 1u << s;
        if (sloc[(1*NSRC + s)*2] == y && sloc[(1*NSRC + s)*2 + 1] == x) smask1 |= 1u << s;
    }
    unsigned smask[2] = { smask0, smask1 };

    // register-resident state: wave fields (own cell) + all 8 CPML memory vars
    float vy[2]  = {0.f, 0.f}, vx[2]  = {0.f, 0.f};
    float syy[2] = {0.f, 0.f}, sxy[2] = {0.f, 0.f}, sxx[2] = {0.f, 0.f};
    float m_vyy[2]  = {0.f, 0.f}, m_vyx[2]  = {0.f, 0.f};
    float m_vxy[2]  = {0.f, 0.f}, m_vxx[2]  = {0.f, 0.f};
    float m_syyy[2] = {0.f, 0.f}, m_sxyy[2] = {0.f, 0.f};
    float m_sxyx[2] = {0.f, 0.f}, m_sxxx[2] = {0.f, 0.f};

    // zero the global fields for this run
#pragma unroll
    for (int b = 0; b < NSHOT; b++) {
        int i = b * NS1 + o;
        g_vy[i] = 0.f; g_vx[i] = 0.f;
        g_syy[i] = 0.f; g_sxy[i] = 0.f; g_sxx[i] = 0.f;
    }
    gbar(++ph);

    const float C1 = 1.125f;
    const float C2 = -1.0f / 24.0f;

    for (int t = 0; t < NT; t++) {
        // ---------------- velocity phase ----------------
#pragma unroll
        for (int b = 0; b < NSHOT; b++) {
            const int base = b * NS1;
            float d, m;

            d = (C1 * (syy[b] - g_syy[base + oym1])
               + C2 * (g_syy[base + oyp1] - g_syy[base + oym2])) * IDHF;
            m = m_syyy[b]; m = byv * m + (byv - 1.0f) * d; m_syyy[b] = m;
            float ay = d + m;

            d = (C1 * (g_sxy[base + oxp1] - sxy[b])
               + C2 * (g_sxy[base + oxp2] - g_sxy[base + oxm1])) * IDHF;
            m = m_sxyx[b]; m = bxv * m + (bxv - 1.0f) * d; m_sxyx[b] = m;
            ay += d + m;

            vy[b] += DTF * bv * ay;

            d = (C1 * (sxx[b] - g_sxx[base + oxm1])
               + C2 * (g_sxx[base + oxp1] - g_sxx[base + oxm2])) * IDHF;
            m = m_sxxx[b]; m = bxv * m + (bxv - 1.0f) * d; m_sxxx[b] = m;
            float ax = d + m;

            d = (C1 * (g_sxy[base + oyp1] - sxy[b])
               + C2 * (g_sxy[base + oyp2] - g_sxy[base + oym1])) * IDHF;
            m = m_sxyy[b]; m = byv * m + (byv - 1.0f) * d; m_sxyy[b] = m;
            ax += d + m;

            vx[b] += DTF * bv * ax;

            if (smask[b]) {
#pragma unroll
                for (int s = 0; s < NSRC; s++)
                    if (smask[b] & (1u << s))
                        vy[b] += DTF * amps[(b*NSRC + s)*NT + t] * bv;
            }
            vy[b] *= mk;
            vx[b] *= mk;
            g_vy[base + o] = vy[b];
            g_vx[base + o] = vx[b];
        }
        gbar(++ph);

        // receivers: vy is not modified during stress phase -> race-free
        if (cid < NSHOT * NREC) {
            int rb = cid / NREC, r = cid - rb * NREC;
            int ry = rloc[(rb*NREC + r)*2];
            int rx = rloc[(rb*NREC + r)*2 + 1];
            g_recs[(t*NSHOT + rb)*NREC + r] = g_vy[rb*NS1 + ry*NG + rx];
        }

        // ---------------- stress phase ----------------
#pragma unroll
        for (int b = 0; b < NSHOT; b++) {
            const int base = b * NS1;
            float d, m;

            d = (C1 * (g_vy[base + oyp1] - vy[b])
               + C2 * (g_vy[base + oyp2] - g_vy[base + oym1])) * IDHF;
            m = m_vyy[b]; m = byv * m + (byv - 1.0f) * d; m_vyy[b] = m;
            float e1 = d + m;

            d = (C1 * (vx[b] - g_vx[base + oxm1])
               + C2 * (g_vx[base + oxp1] - g_vx[base + oxm2])) * IDHF;
            m = m_vxx[b]; m = bxv * m + (bxv - 1.0f) * d; m_vxx[b] = m;
            float e2 = d + m;

            syy[b] = (syy[b] + DTF * (l2m * e1 + lam * e2)) * mk;
            sxx[b] = (sxx[b] + DTF * (l2m * e2 + lam * e1)) * mk;

            d = (C1 * (g_vy[base + oxp1] - vy[b])
               + C2 * (g_vy[base + oxp2] - g_vy[base + oxm1])) * IDHF;
            m = m_vyx[b]; m = bxv * m + (bxv - 1.0f) * d; m_vyx[b] = m;
            float g = d + m;

            d = (C1 * (vx[b] - g_vx[base + oym1])
               + C2 * (g_vx[base + oyp1] - g_vx[base + oym2])) * IDHF;
            m = m_vxy[b]; m = byv * m + (byv - 1.0f) * d; m_vxy[b] = m;
            g += d + m;

            sxy[b] = (sxy[b] + DTF * muv * g) * mk;

            g_syy[base + o] = syy[b];
            g_sxy[base + o] = sxy[b];
            g_sxx[base + o] = sxx[b];
        }
        gbar(++ph);
    }

    // ---------------- finalize: average adjacent time samples ----------------
    const int total = NSHOT * NREC * (NT - 1);
    if (cid < total) {
        int t = cid % (NT - 1);
        int r = (cid / (NT - 1)) % NREC;
        int b = cid / ((NT - 1) * NREC);
        out[cid] = 0.5f * (g_recs[((t + 1)*NSHOT + b)*NREC + r]
                         + g_recs[(t      *NSHOT + b)*NREC + r]);
    }
}

extern "C" void kernel_launch(void* const* d_in, const int* in_sizes, int n_in,
                              void* d_out, int out_size)
{
    const float* lamb = (const float*)d_in[0];
    const float* mu   = (const float*)d_in[1];
    const float* buoy = (const float*)d_in[2];
    const float* amps = (const float*)d_in[3];
    const int*   sloc = (const int*)d_in[4];
    const int*   rloc = (const int*)d_in[5];
    float* out = (float*)d_out;

    sim_kernel<<<NBLK, TPB>>>(lamb, mu, buoy, amps, sloc, rloc, out);
}